// round 2
// baseline (speedup 1.0000x reference)
#include <cuda_runtime.h>
#include <math.h>

// Problem constants
#define NN  32
#define PPd 6
#define Cd  128
#define Td  64
#define Vd  25
#define Sd  3
#define CId 32
#define NPd   (NN*PPd)        // 192
#define NPVd  (NPd*Vd)        // 4800
#define SLAB  (Cd*Td)         // 8192 floats per (n,p,v)
#define QKOd  (2*Sd*CId)      // 192
#define TOTd  (NPVd*SLAB)     // 39321600
#define CNTf  307200.0f       // N*P*T*V
#define EPSf  1e-5f
#define NEGf  0.1f

// Scratch (module-scope device globals; allocated at load, not in kernel_launch)
__device__ float g_x0[TOTd];
__device__ float g_x1[TOTd];
__device__ float g_y1[TOTd];
__device__ float g_z [TOTd];
__device__ float g_qk [NPVd*QKOd*Td];
__device__ float g_att[NN*Sd*PPd*Td*Td];
__device__ float g_sum[Cd];
__device__ float g_sq [Cd];
__device__ float g_wt_in [Cd*QKOd];     // [c][o]
__device__ float g_wt_out[Sd*Cd*Cd];    // [s*C+c][o]
__device__ float g_wt_ff [Cd*Cd];       // [c][o]

__device__ __forceinline__ float lrelu(float x){ return x >= 0.f ? x : NEGf*x; }

// ---------------------------------------------------------------------------
// Weight transposes (tiny, once per launch)
__global__ void k_prep(const float* __restrict__ w_in,
                       const float* __restrict__ w_out,
                       const float* __restrict__ w_ff){
  int i = blockIdx.x*blockDim.x + threadIdx.x;
  if (i < Cd*QKOd){ int c=i/QKOd, o=i%QKOd; g_wt_in[i] = w_in[o*Cd + c]; }
  int j = i - Cd*QKOd;
  if (j >= 0 && j < Sd*Cd*Cd){ int sc=j/Cd, o=j%Cd; g_wt_out[j] = w_out[o*(Sd*Cd) + sc]; }
  int k = i - Cd*QKOd - Sd*Cd*Cd;
  if (k >= 0 && k < Cd*Cd){ int c=k/Cd, o=k%Cd; g_wt_ff[k] = w_ff[o*Cd + c]; }
}

// ---------------------------------------------------------------------------
// Input transpose: x[(n,p)][c][t][v]  ->  g_x0[(n,p)][v][c][t]
__global__ void k_tin(const float* __restrict__ x){
  __shared__ float tile[32][33];
  int np = blockIdx.y, m0 = blockIdx.x*32;
  const float* src = x + (size_t)np*(Cd*Td*Vd);
  float* dst = g_x0 + (size_t)np*(Vd*SLAB);
  int tx = threadIdx.x, ty = threadIdx.y;
  #pragma unroll
  for (int k=0;k<4;k++){
    int m = m0 + ty + k*8;
    if (tx < Vd) tile[ty+k*8][tx] = src[(size_t)m*Vd + tx];
  }
  __syncthreads();
  #pragma unroll
  for (int k=0;k<4;k++){
    int v = ty + k*8;
    if (v < Vd) dst[(size_t)v*SLAB + m0 + tx] = tile[tx][v];
  }
}

// Output transpose: src[(n,p)][v][c][t] -> dst[(n,p)][c][t][v]
__global__ void k_tout(const float* __restrict__ srcb, float* __restrict__ dst){
  __shared__ float tile[32][33];
  int np = blockIdx.y, m0 = blockIdx.x*32;
  const float* src = srcb + (size_t)np*(Vd*SLAB);
  float* d = dst + (size_t)np*(Cd*Td*Vd);
  int tx = threadIdx.x, ty = threadIdx.y;
  #pragma unroll
  for (int k=0;k<4;k++){
    int v = ty + k*8;
    if (v < Vd) tile[v][tx] = src[(size_t)v*SLAB + m0 + tx];
  }
  __syncthreads();
  #pragma unroll
  for (int k=0;k<4;k++){
    int m = m0 + ty + k*8;
    if (tx < Vd) d[(size_t)m*Vd + tx] = tile[tx][ty + k*8];
  }
}

// ---------------------------------------------------------------------------
// QK conv: per (n,p,v):  QK[o][t] = b_in[o] + sum_c w_in[o][c] * X[c][t]
// 192x64x128 GEMM per block. 16x16 threads, 12x4 register tile.
__global__ void __launch_bounds__(256) k_qk(const float* __restrict__ in,
                                            const float* __restrict__ b_in){
  extern __shared__ float sm[];
  float* Xs  = sm;            // 8192
  float* Wch = sm + SLAB;     // 16*192
  int npv = blockIdx.x;
  int tid = threadIdx.x, tx = tid & 15, ty = tid >> 4;
  const float4* xin4 = (const float4*)(in + (size_t)npv*SLAB);
  for (int i = tid; i < SLAB/4; i += 256) ((float4*)Xs)[i] = xin4[i];
  float acc[12][4];
  #pragma unroll
  for (int i=0;i<12;i++){ acc[i][0]=acc[i][1]=acc[i][2]=acc[i][3]=0.f; }
  for (int c0=0;c0<Cd;c0+=16){
    __syncthreads();
    for (int i=tid;i<16*QKOd;i+=256) Wch[i] = g_wt_in[(size_t)(c0 + i/QKOd)*QKOd + (i%QKOd)];
    __syncthreads();
    #pragma unroll 4
    for (int cc=0;cc<16;cc++){
      float4 xr = *(const float4*)&Xs[(c0+cc)*Td + tx*4];
      #pragma unroll
      for (int i=0;i<12;i++){
        float w = Wch[cc*QKOd + ty*12 + i];
        acc[i][0]+=w*xr.x; acc[i][1]+=w*xr.y; acc[i][2]+=w*xr.z; acc[i][3]+=w*xr.w;
      }
    }
  }
  float* outp = g_qk + (size_t)npv*QKOd*Td;
  #pragma unroll
  for (int i=0;i<12;i++){
    int o = ty*12 + i;
    float b = b_in[o];
    *(float4*)&outp[o*Td + tx*4] =
      make_float4(acc[i][0]+b, acc[i][1]+b, acc[i][2]+b, acc[i][3]+b);
  }
}

// ---------------------------------------------------------------------------
// Attention: per (n,s,p): att[t,q] = bias + tanh( sum_{c,v} q[c,t,v]k[c,q,v] / 800 )*alpha
__global__ void __launch_bounds__(256) k_att(const float* __restrict__ attb,
                                             const float* __restrict__ alphat){
  __shared__ float qv[CId*Td];
  __shared__ float kv[CId*Td];
  int b = blockIdx.x;               // ((n*S+s)*P+p)
  int p = b % PPd; int s = (b/PPd) % Sd; int n = b/(PPd*Sd);
  int np = n*PPd + p;
  int tid = threadIdx.x, tx = tid & 15, ty = tid >> 4;
  float acc[4][4];
  #pragma unroll
  for (int i=0;i<4;i++){ acc[i][0]=acc[i][1]=acc[i][2]=acc[i][3]=0.f; }
  for (int v=0; v<Vd; v++){
    size_t base = ((size_t)(np*Vd + v))*QKOd*Td;
    const float4* q4 = (const float4*)(g_qk + base + (size_t)(s*CId)*Td);
    const float4* k4 = (const float4*)(g_qk + base + (size_t)(Sd*CId + s*CId)*Td);
    __syncthreads();
    for (int i=tid; i<CId*Td/4; i+=256){ ((float4*)qv)[i]=q4[i]; ((float4*)kv)[i]=k4[i]; }
    __syncthreads();
    #pragma unroll 4
    for (int c=0;c<CId;c++){
      float qr[4], kr[4];
      #pragma unroll
      for (int i=0;i<4;i++) qr[i]=qv[c*Td + ty*4 + i];
      #pragma unroll
      for (int j=0;j<4;j++) kr[j]=kv[c*Td + tx*4 + j];
      #pragma unroll
      for (int i=0;i<4;i++)
        #pragma unroll
        for (int j=0;j<4;j++) acc[i][j] += qr[i]*kr[j];
    }
  }
  float al = alphat[s];
  float* attp = g_att + (size_t)b*Td*Td;
  const float* bp = attb + (size_t)s*Td*Td;
  #pragma unroll
  for (int i=0;i<4;i++){
    int t = ty*4 + i;
    #pragma unroll
    for (int j=0;j<4;j++){
      int q = tx*4 + j;
      attp[t*Td+q] = bp[t*Td+q] + tanhf(acc[i][j]*(1.f/800.f))*al;
    }
  }
}

// ---------------------------------------------------------------------------
// Fused attention-apply + S*C->C conv + BN stats.
// per (n,p,v): Ys = X @ A_s (128x64x64), Z = sum_s W_s @ Ys + b (128x64x128 x3)
__global__ void __launch_bounds__(256,2) k_av(const float* __restrict__ in,
                                              const float* __restrict__ b_out){
  extern __shared__ float sm[];
  float* Xs  = sm;                      // 8192
  float* Ys  = sm + SLAB;               // 8192
  float* As  = sm + 2*SLAB;             // 4096
  float* Wch = sm + 2*SLAB + Td*Td;     // 2048
  int npv = blockIdx.x;
  int np = npv / Vd;
  int p = np % PPd, n = np / PPd;
  int tid = threadIdx.x, tx = tid & 15, ty = tid >> 4;

  const float4* xin4 = (const float4*)(in + (size_t)npv*SLAB);
  for (int i=tid; i<SLAB/4; i+=256) ((float4*)Xs)[i] = xin4[i];

  float acc[8][4];
  #pragma unroll
  for (int i=0;i<8;i++){ acc[i][0]=acc[i][1]=acc[i][2]=acc[i][3]=0.f; }

  for (int s=0;s<Sd;s++){
    __syncthreads();
    const float4* a4 = (const float4*)(g_att + ((size_t)((n*Sd+s)*PPd+p))*Td*Td);
    for (int i=tid; i<Td*Td/4; i+=256) ((float4*)As)[i] = a4[i];
    __syncthreads();

    float ya[8][4];
    #pragma unroll
    for (int i=0;i<8;i++){ ya[i][0]=ya[i][1]=ya[i][2]=ya[i][3]=0.f; }
    #pragma unroll 4
    for (int t=0;t<Td;t++){
      float4 ar = *(const float4*)&As[t*Td + tx*4];
      #pragma unroll
      for (int i=0;i<8;i++){
        float xv = Xs[(ty*8+i)*Td + t];
        ya[i][0]+=xv*ar.x; ya[i][1]+=xv*ar.y; ya[i][2]+=xv*ar.z; ya[i][3]+=xv*ar.w;
      }
    }
    #pragma unroll
    for (int i=0;i<8;i++)
      *(float4*)&Ys[(ty*8+i)*Td + tx*4] = make_float4(ya[i][0],ya[i][1],ya[i][2],ya[i][3]);

    for (int c0=0;c0<Cd;c0+=16){
      __syncthreads();
      for (int i=tid;i<16*Cd;i+=256)
        Wch[i] = g_wt_out[(size_t)(s*Cd + c0 + i/Cd)*Cd + (i%Cd)];
      __syncthreads();
      #pragma unroll 4
      for (int cc=0;cc<16;cc++){
        float4 yr = *(const float4*)&Ys[(c0+cc)*Td + tx*4];
        #pragma unroll
        for (int i=0;i<8;i++){
          float w = Wch[cc*Cd + ty*8 + i];
          acc[i][0]+=w*yr.x; acc[i][1]+=w*yr.y; acc[i][2]+=w*yr.z; acc[i][3]+=w*yr.w;
        }
      }
    }
  }

  float* zp = g_z + (size_t)npv*SLAB;
  #pragma unroll
  for (int i=0;i<8;i++){
    int o = ty*8 + i;
    float b = b_out[o];
    float z0=acc[i][0]+b, z1=acc[i][1]+b, z2=acc[i][2]+b, z3=acc[i][3]+b;
    *(float4*)&zp[o*Td + tx*4] = make_float4(z0,z1,z2,z3);
    float s1 = z0+z1+z2+z3;
    float s2 = z0*z0+z1*z1+z2*z2+z3*z3;
    #pragma unroll
    for (int off=8; off>0; off>>=1){
      s1 += __shfl_xor_sync(0xffffffffu, s1, off, 16);
      s2 += __shfl_xor_sync(0xffffffffu, s2, off, 16);
    }
    if (tx==0){ atomicAdd(&g_sum[o], s1); atomicAdd(&g_sq[o], s2); }
  }
}

// ---------------------------------------------------------------------------
// FF conv: per (n,p,v): Z2 = W_ff @ Y1 + b (128x64x128) + BN stats
__global__ void __launch_bounds__(256) k_ff(const float* __restrict__ in,
                                            const float* __restrict__ b_ff){
  extern __shared__ float sm[];
  float* Xs  = sm;           // 8192
  float* Wch = sm + SLAB;    // 2048
  int npv = blockIdx.x;
  int tid = threadIdx.x, tx = tid & 15, ty = tid >> 4;
  const float4* xin4 = (const float4*)(in + (size_t)npv*SLAB);
  for (int i=tid; i<SLAB/4; i+=256) ((float4*)Xs)[i] = xin4[i];
  float acc[8][4];
  #pragma unroll
  for (int i=0;i<8;i++){ acc[i][0]=acc[i][1]=acc[i][2]=acc[i][3]=0.f; }
  for (int c0=0;c0<Cd;c0+=16){
    __syncthreads();
    for (int i=tid;i<16*Cd;i+=256)
      Wch[i] = g_wt_ff[(size_t)(c0 + i/Cd)*Cd + (i%Cd)];
    __syncthreads();
    #pragma unroll 4
    for (int cc=0;cc<16;cc++){
      float4 xr = *(const float4*)&Xs[(c0+cc)*Td + tx*4];
      #pragma unroll
      for (int i=0;i<8;i++){
        float w = Wch[cc*Cd + ty*8 + i];
        acc[i][0]+=w*xr.x; acc[i][1]+=w*xr.y; acc[i][2]+=w*xr.z; acc[i][3]+=w*xr.w;
      }
    }
  }
  float* zp = g_z + (size_t)npv*SLAB;
  #pragma unroll
  for (int i=0;i<8;i++){
    int o = ty*8 + i;
    float b = b_ff[o];
    float z0=acc[i][0]+b, z1=acc[i][1]+b, z2=acc[i][2]+b, z3=acc[i][3]+b;
    *(float4*)&zp[o*Td + tx*4] = make_float4(z0,z1,z2,z3);
    float s1 = z0+z1+z2+z3;
    float s2 = z0*z0+z1*z1+z2*z2+z3*z3;
    #pragma unroll
    for (int off=8; off>0; off>>=1){
      s1 += __shfl_xor_sync(0xffffffffu, s1, off, 16);
      s2 += __shfl_xor_sync(0xffffffffu, s2, off, 16);
    }
    if (tx==0){ atomicAdd(&g_sum[o], s1); atomicAdd(&g_sq[o], s2); }
  }
}

// ---------------------------------------------------------------------------
// BN apply + residual + leaky
__global__ void k_bnres(const float* __restrict__ res, const float* __restrict__ z,
                        float* __restrict__ out,
                        const float* __restrict__ gamma, const float* __restrict__ beta){
  size_t i4 = (size_t)blockIdx.x*256 + threadIdx.x;
  int c = (int)((i4 >> 4) & 127);
  float mu  = g_sum[c] * (1.0f/CNTf);
  float var = g_sq[c]  * (1.0f/CNTf) - mu*mu;
  float sc  = gamma[c] * rsqrtf(var + EPSf);
  float sh  = beta[c] - mu*sc;
  float4 zr = ((const float4*)z)[i4];
  float4 rr = ((const float4*)res)[i4];
  float4 o;
  o.x = lrelu(rr.x + zr.x*sc + sh);
  o.y = lrelu(rr.y + zr.y*sc + sh);
  o.z = lrelu(rr.z + zr.z*sc + sh);
  o.w = lrelu(rr.w + zr.w*sc + sh);
  ((float4*)out)[i4] = o;
}

__global__ void k_zero(){
  int i = threadIdx.x;
  if (i < Cd){ g_sum[i] = 0.f; g_sq[i] = 0.f; }
}

// ---------------------------------------------------------------------------
extern "C" void kernel_launch(void* const* d_in, const int* in_sizes, int n_in,
                              void* d_out, int out_size){
  const float* x     = (const float*)d_in[0];
  const float* att1  = (const float*)d_in[1];
  const float* att2  = (const float*)d_in[2];
  const float* alpt  = (const float*)d_in[3];
  const float* w_in  = (const float*)d_in[4];
  const float* b_in  = (const float*)d_in[5];
  const float* w_out = (const float*)d_in[6];
  const float* b_out = (const float*)d_in[7];
  const float* g_o   = (const float*)d_in[8];
  const float* be_o  = (const float*)d_in[9];
  const float* w_ff  = (const float*)d_in[10];
  const float* b_ff  = (const float*)d_in[11];
  const float* g_f   = (const float*)d_in[12];
  const float* be_f  = (const float*)d_in[13];

  float *px0, *px1, *py1, *pz;
  cudaGetSymbolAddress((void**)&px0, g_x0);
  cudaGetSymbolAddress((void**)&px1, g_x1);
  cudaGetSymbolAddress((void**)&py1, g_y1);
  cudaGetSymbolAddress((void**)&pz,  g_z);

  const int SM_QK = (SLAB + 16*QKOd)*4;           // 45056
  const int SM_AV = (2*SLAB + Td*Td + 16*Cd)*4;   // 90112
  const int SM_FF = (SLAB + 16*Cd)*4;             // 40960
  cudaFuncSetAttribute(k_av, cudaFuncAttributeMaxDynamicSharedMemorySize, SM_AV);

  k_prep<<<352,256>>>(w_in, w_out, w_ff);
  k_tin<<<dim3(256,192), dim3(32,8)>>>(x);

  auto run_block = [&](const float* attb, const float* inb, float* outb){
    k_qk <<<NPVd,256,SM_QK>>>(inb, b_in);
    k_att<<<NN*Sd*PPd,256>>>(attb, alpt);
    k_zero<<<1,128>>>();
    k_av <<<NPVd,256,SM_AV>>>(inb, b_out);
    k_bnres<<<TOTd/4/256,256>>>(inb, pz, py1, g_o, be_o);
    k_zero<<<1,128>>>();
    k_ff <<<NPVd,256,SM_FF>>>(py1, b_ff);
    k_bnres<<<TOTd/4/256,256>>>(py1, pz, outb, g_f, be_f);
  };

  run_block(att1, px0, px1);   // block 1: x0 -> x1
  run_block(att2, px1, px0);   // block 2: x1 -> x0

  k_tout<<<dim3(256,192), dim3(32,8)>>>(px0, (float*)d_out);
}

// round 3
// speedup vs baseline: 1.8099x; 1.8099x over previous
#include <cuda_runtime.h>
#include <math.h>

// Problem constants
#define NN  32
#define PPd 6
#define Cd  128
#define Td  64
#define Vd  25
#define Sd  3
#define CId 32
#define NPd   (NN*PPd)        // 192
#define NPVd  (NPd*Vd)        // 4800
#define SLAB  (Cd*Td)         // 8192 floats per (n,p,v)
#define QKOd  (2*Sd*CId)      // 192
#define TOTd  (NPVd*SLAB)     // 39321600
#define CNTf  307200.0f       // N*P*T*V
#define EPSf  1e-5f
#define NEGf  0.1f

// Scratch
__device__ float g_x0[TOTd];
__device__ float g_x1[TOTd];
__device__ float g_y1[TOTd];
__device__ float g_z [TOTd];
__device__ float g_qk [NPVd*QKOd*Td];
__device__ float g_att[NN*Sd*PPd*Td*Td];
__device__ float g_sum[Cd];
__device__ float g_sq [Cd];

__device__ __forceinline__ float lrelu(float x){ return x >= 0.f ? x : NEGf*x; }

__device__ __forceinline__ float to_tf32(float x){
  unsigned u; asm("cvt.rna.tf32.f32 %0, %1;" : "=r"(u) : "f"(x));
  return __uint_as_float(u);
}
__device__ __forceinline__ void st_tf32_f4(float* dst, float4 v){
  dst[0]=to_tf32(v.x); dst[1]=to_tf32(v.y); dst[2]=to_tf32(v.z); dst[3]=to_tf32(v.w);
}
__device__ __forceinline__ void mma8(float c[4], const float a[4], const float b[2]){
  asm volatile(
    "mma.sync.aligned.m16n8k8.row.col.f32.tf32.tf32.f32 "
    "{%0,%1,%2,%3},{%4,%5,%6,%7},{%8,%9},{%0,%1,%2,%3};\n"
    : "+f"(c[0]),"+f"(c[1]),"+f"(c[2]),"+f"(c[3])
    : "r"(__float_as_uint(a[0])),"r"(__float_as_uint(a[1])),
      "r"(__float_as_uint(a[2])),"r"(__float_as_uint(a[3])),
      "r"(__float_as_uint(b[0])),"r"(__float_as_uint(b[1])));
}

// ---------------------------------------------------------------------------
// Input transpose: x[(n,p)][c][t][v]  ->  g_x0[(n,p)][v][c][t]
__global__ void k_tin(const float* __restrict__ x){
  __shared__ float tile[32][33];
  int np = blockIdx.y, m0 = blockIdx.x*32;
  const float* src = x + (size_t)np*(Cd*Td*Vd);
  float* dst = g_x0 + (size_t)np*(Vd*SLAB);
  int tx = threadIdx.x, ty = threadIdx.y;
  #pragma unroll
  for (int k=0;k<4;k++){
    int m = m0 + ty + k*8;
    if (tx < Vd) tile[ty+k*8][tx] = src[(size_t)m*Vd + tx];
  }
  __syncthreads();
  #pragma unroll
  for (int k=0;k<4;k++){
    int v = ty + k*8;
    if (v < Vd) dst[(size_t)v*SLAB + m0 + tx] = tile[tx][v];
  }
}

// Output transpose: src[(n,p)][v][c][t] -> dst[(n,p)][c][t][v]
__global__ void k_tout(const float* __restrict__ srcb, float* __restrict__ dst){
  __shared__ float tile[32][33];
  int np = blockIdx.y, m0 = blockIdx.x*32;
  const float* src = srcb + (size_t)np*(Vd*SLAB);
  float* d = dst + (size_t)np*(Cd*Td*Vd);
  int tx = threadIdx.x, ty = threadIdx.y;
  #pragma unroll
  for (int k=0;k<4;k++){
    int v = ty + k*8;
    if (v < Vd) tile[v][tx] = src[(size_t)v*SLAB + m0 + tx];
  }
  __syncthreads();
  #pragma unroll
  for (int k=0;k<4;k++){
    int m = m0 + ty + k*8;
    if (tx < Vd) d[(size_t)m*Vd + tx] = tile[tx][ty + k*8];
  }
}

// ---------------------------------------------------------------------------
// QK conv (tensor): per npv  Out[192x64] = W_in[192x128] * X[128x64] + b
// warps: 4 in M (48 rows) x 2 in N (32 cols). K chunked by 32.
__global__ void __launch_bounds__(256,2) k_qk(const float* __restrict__ in,
                                              const float* __restrict__ w_in,
                                              const float* __restrict__ b_in){
  extern __shared__ float sm[];
  float* Xs = sm;              // 128*68
  float* Wc = sm + 128*68;     // 192*36
  int npv = blockIdx.x;
  int tid = threadIdx.x, lane = tid&31, w = tid>>5;
  int m0 = (w&3)*48, n0 = (w>>2)*32;
  int gid = lane>>2, tig = lane&3;

  const float4* xin4 = (const float4*)(in + (size_t)npv*SLAB);
  for (int i=tid;i<2048;i+=256){
    int r = i>>4, c4 = (i&15)<<2;
    st_tf32_f4(&Xs[r*68 + c4], xin4[i]);
  }
  float acc[3][4][4];
  #pragma unroll
  for (int mf=0;mf<3;mf++)
    #pragma unroll
    for (int nf=0;nf<4;nf++){ acc[mf][nf][0]=acc[mf][nf][1]=acc[mf][nf][2]=acc[mf][nf][3]=0.f; }

  for (int c0=0;c0<128;c0+=32){
    __syncthreads();
    for (int i=tid;i<1536;i+=256){
      int o = i>>3, c4 = (i&7)<<2;
      st_tf32_f4(&Wc[o*36 + c4], *(const float4*)&w_in[(size_t)o*128 + c0 + c4]);
    }
    __syncthreads();
    #pragma unroll
    for (int kt=0;kt<4;kt++){
      int kk = kt*8;
      float a[3][4], b[4][2];
      #pragma unroll
      for (int mf=0;mf<3;mf++){
        int r = m0 + mf*16 + gid;
        a[mf][0] = Wc[r*36 + kk + tig];
        a[mf][1] = Wc[(r+8)*36 + kk + tig];
        a[mf][2] = Wc[r*36 + kk + 4 + tig];
        a[mf][3] = Wc[(r+8)*36 + kk + 4 + tig];
      }
      #pragma unroll
      for (int nf=0;nf<4;nf++){
        int col = n0 + nf*8 + gid;
        b[nf][0] = Xs[(c0+kk+tig)*68 + col];
        b[nf][1] = Xs[(c0+kk+4+tig)*68 + col];
      }
      #pragma unroll
      for (int mf=0;mf<3;mf++)
        #pragma unroll
        for (int nf=0;nf<4;nf++) mma8(acc[mf][nf], a[mf], b[nf]);
    }
  }
  float* outp = g_qk + (size_t)npv*QKOd*Td;
  #pragma unroll
  for (int mf=0;mf<3;mf++){
    int r = m0 + mf*16 + gid;
    float b0 = b_in[r], b1 = b_in[r+8];
    #pragma unroll
    for (int nf=0;nf<4;nf++){
      int col = n0 + nf*8 + 2*tig;
      *(float2*)&outp[r*64 + col]     = make_float2(acc[mf][nf][0]+b0, acc[mf][nf][1]+b0);
      *(float2*)&outp[(r+8)*64 + col] = make_float2(acc[mf][nf][2]+b1, acc[mf][nf][3]+b1);
    }
  }
}

// ---------------------------------------------------------------------------
// Attention: per (n,s,p): att[t,q] = bias + tanh( sum_{c,v} q[c,t,v]k[c,q,v] / 800 )*alpha
__global__ void __launch_bounds__(256) k_att(const float* __restrict__ attb,
                                             const float* __restrict__ alphat){
  __shared__ float qv[CId*Td];
  __shared__ float kv[CId*Td];
  int b = blockIdx.x;               // ((n*S+s)*P+p)
  int p = b % PPd; int s = (b/PPd) % Sd; int n = b/(PPd*Sd);
  int np = n*PPd + p;
  int tid = threadIdx.x, tx = tid & 15, ty = tid >> 4;
  float acc[4][4];
  #pragma unroll
  for (int i=0;i<4;i++){ acc[i][0]=acc[i][1]=acc[i][2]=acc[i][3]=0.f; }
  for (int v=0; v<Vd; v++){
    size_t base = ((size_t)(np*Vd + v))*QKOd*Td;
    const float4* q4 = (const float4*)(g_qk + base + (size_t)(s*CId)*Td);
    const float4* k4 = (const float4*)(g_qk + base + (size_t)(Sd*CId + s*CId)*Td);
    __syncthreads();
    for (int i=tid; i<CId*Td/4; i+=256){ ((float4*)qv)[i]=q4[i]; ((float4*)kv)[i]=k4[i]; }
    __syncthreads();
    #pragma unroll 4
    for (int c=0;c<CId;c++){
      float qr[4], kr[4];
      #pragma unroll
      for (int i=0;i<4;i++) qr[i]=qv[c*Td + ty*4 + i];
      #pragma unroll
      for (int j=0;j<4;j++) kr[j]=kv[c*Td + tx*4 + j];
      #pragma unroll
      for (int i=0;i<4;i++)
        #pragma unroll
        for (int j=0;j<4;j++) acc[i][j] += qr[i]*kr[j];
    }
  }
  float al = alphat[s];
  float* attp = g_att + (size_t)b*Td*Td;
  const float* bp = attb + (size_t)s*Td*Td;
  #pragma unroll
  for (int i=0;i<4;i++){
    int t = ty*4 + i;
    #pragma unroll
    for (int j=0;j<4;j++){
      int q = tx*4 + j;
      attp[t*Td+q] = bp[t*Td+q] + tanhf(acc[i][j]*(1.f/800.f))*al;
    }
  }
}

// ---------------------------------------------------------------------------
// Fused attention-apply + S*C->C conv + BN stats (tensor).
// per npv: for s: Ys[128x64] = X*A_s (K=64);  Z += W_s[128x128]*Ys (K=128)
__global__ void __launch_bounds__(256,2) k_av(const float* __restrict__ in,
                                              const float* __restrict__ w_out,
                                              const float* __restrict__ b_out){
  extern __shared__ float sm[];
  float* Xs = sm;              // 128*68 = 8704
  float* Ys = sm + 8704;       // 128*68 = 8704
  float* As = sm + 17408;      // 64*68  = 4352
  float* Wc = sm + 21760;      // 128*36 = 4608
  int npv = blockIdx.x;
  int np = npv / Vd;
  int p = np % PPd, n = np / PPd;
  int tid = threadIdx.x, lane = tid&31, w = tid>>5;
  int m0 = (w&3)*32, n0 = (w>>2)*32;
  int gid = lane>>2, tig = lane&3;

  const float4* xin4 = (const float4*)(in + (size_t)npv*SLAB);
  for (int i=tid;i<2048;i+=256){
    int r = i>>4, c4 = (i&15)<<2;
    st_tf32_f4(&Xs[r*68 + c4], xin4[i]);
  }
  float zacc[2][4][4];
  #pragma unroll
  for (int mf=0;mf<2;mf++)
    #pragma unroll
    for (int nf=0;nf<4;nf++){ zacc[mf][nf][0]=zacc[mf][nf][1]=zacc[mf][nf][2]=zacc[mf][nf][3]=0.f; }

  for (int s=0;s<Sd;s++){
    __syncthreads();
    const float4* a4 = (const float4*)(g_att + ((size_t)((n*Sd+s)*PPd+p))*Td*Td);
    for (int i=tid;i<1024;i+=256){
      int r = i>>4, c4 = (i&15)<<2;
      st_tf32_f4(&As[r*68 + c4], a4[i]);
    }
    __syncthreads();

    // Stage 1: Ys = X * A_s   (m=c rows of X, n=q, k=t)
    float yacc[2][4][4];
    #pragma unroll
    for (int mf=0;mf<2;mf++)
      #pragma unroll
      for (int nf=0;nf<4;nf++){ yacc[mf][nf][0]=yacc[mf][nf][1]=yacc[mf][nf][2]=yacc[mf][nf][3]=0.f; }
    #pragma unroll
    for (int kt=0;kt<8;kt++){
      int kk = kt*8;
      float a[2][4], b[4][2];
      #pragma unroll
      for (int mf=0;mf<2;mf++){
        int r = m0 + mf*16 + gid;
        a[mf][0] = Xs[r*68 + kk + tig];
        a[mf][1] = Xs[(r+8)*68 + kk + tig];
        a[mf][2] = Xs[r*68 + kk + 4 + tig];
        a[mf][3] = Xs[(r+8)*68 + kk + 4 + tig];
      }
      #pragma unroll
      for (int nf=0;nf<4;nf++){
        int col = n0 + nf*8 + gid;
        b[nf][0] = As[(kk+tig)*68 + col];
        b[nf][1] = As[(kk+4+tig)*68 + col];
      }
      #pragma unroll
      for (int mf=0;mf<2;mf++)
        #pragma unroll
        for (int nf=0;nf<4;nf++) mma8(yacc[mf][nf], a[mf], b[nf]);
    }
    // write Ys (tf32-rounded)
    #pragma unroll
    for (int mf=0;mf<2;mf++){
      int r = m0 + mf*16 + gid;
      #pragma unroll
      for (int nf=0;nf<4;nf++){
        int col = n0 + nf*8 + 2*tig;
        Ys[r*68 + col]       = to_tf32(yacc[mf][nf][0]);
        Ys[r*68 + col + 1]   = to_tf32(yacc[mf][nf][1]);
        Ys[(r+8)*68 + col]   = to_tf32(yacc[mf][nf][2]);
        Ys[(r+8)*68 + col+1] = to_tf32(yacc[mf][nf][3]);
      }
    }

    // Stage 2: Z += W_s * Ys   (m=o, k=c chunked by 32, n=q)
    for (int c0=0;c0<128;c0+=32){
      __syncthreads();
      for (int i=tid;i<1024;i+=256){
        int o = i>>3, c4 = (i&7)<<2;
        st_tf32_f4(&Wc[o*36 + c4],
                   *(const float4*)&w_out[(size_t)o*(Sd*Cd) + s*Cd + c0 + c4]);
      }
      __syncthreads();
      #pragma unroll
      for (int kt=0;kt<4;kt++){
        int kk = kt*8;
        float a[2][4], b[4][2];
        #pragma unroll
        for (int mf=0;mf<2;mf++){
          int r = m0 + mf*16 + gid;
          a[mf][0] = Wc[r*36 + kk + tig];
          a[mf][1] = Wc[(r+8)*36 + kk + tig];
          a[mf][2] = Wc[r*36 + kk + 4 + tig];
          a[mf][3] = Wc[(r+8)*36 + kk + 4 + tig];
        }
        #pragma unroll
        for (int nf=0;nf<4;nf++){
          int col = n0 + nf*8 + gid;
          b[nf][0] = Ys[(c0+kk+tig)*68 + col];
          b[nf][1] = Ys[(c0+kk+4+tig)*68 + col];
        }
        #pragma unroll
        for (int mf=0;mf<2;mf++)
          #pragma unroll
          for (int nf=0;nf<4;nf++) mma8(zacc[mf][nf], a[mf], b[nf]);
      }
    }
  }

  // epilogue: bias, store g_z, BN stats
  float* zp = g_z + (size_t)npv*SLAB;
  #pragma unroll
  for (int mf=0;mf<2;mf++){
    int r = m0 + mf*16 + gid;
    float bo0 = b_out[r], bo1 = b_out[r+8];
    float s0a=0.f, s0b=0.f, s1a=0.f, s1b=0.f;
    #pragma unroll
    for (int nf=0;nf<4;nf++){
      int col = n0 + nf*8 + 2*tig;
      float z00 = zacc[mf][nf][0]+bo0, z01 = zacc[mf][nf][1]+bo0;
      float z10 = zacc[mf][nf][2]+bo1, z11 = zacc[mf][nf][3]+bo1;
      *(float2*)&zp[r*64 + col]     = make_float2(z00, z01);
      *(float2*)&zp[(r+8)*64 + col] = make_float2(z10, z11);
      s0a += z00+z01; s0b += z00*z00+z01*z01;
      s1a += z10+z11; s1b += z10*z10+z11*z11;
    }
    #pragma unroll
    for (int off=1; off<4; off<<=1){
      s0a += __shfl_xor_sync(0xffffffffu, s0a, off);
      s0b += __shfl_xor_sync(0xffffffffu, s0b, off);
      s1a += __shfl_xor_sync(0xffffffffu, s1a, off);
      s1b += __shfl_xor_sync(0xffffffffu, s1b, off);
    }
    if (tig==0){
      atomicAdd(&g_sum[r], s0a);   atomicAdd(&g_sq[r], s0b);
      atomicAdd(&g_sum[r+8], s1a); atomicAdd(&g_sq[r+8], s1b);
    }
  }
}

// ---------------------------------------------------------------------------
// FF conv (tensor): Out[128x64] = W_ff[128x128] * X[128x64] + b, with BN stats
__global__ void __launch_bounds__(256,2) k_ff(const float* __restrict__ in,
                                              const float* __restrict__ w_ff,
                                              const float* __restrict__ b_ff){
  extern __shared__ float sm[];
  float* Xs = sm;              // 128*68
  float* Wc = sm + 8704;       // 128*36
  int npv = blockIdx.x;
  int tid = threadIdx.x, lane = tid&31, w = tid>>5;
  int m0 = (w&3)*32, n0 = (w>>2)*32;
  int gid = lane>>2, tig = lane&3;

  const float4* xin4 = (const float4*)(in + (size_t)npv*SLAB);
  for (int i=tid;i<2048;i+=256){
    int r = i>>4, c4 = (i&15)<<2;
    st_tf32_f4(&Xs[r*68 + c4], xin4[i]);
  }
  float acc[2][4][4];
  #pragma unroll
  for (int mf=0;mf<2;mf++)
    #pragma unroll
    for (int nf=0;nf<4;nf++){ acc[mf][nf][0]=acc[mf][nf][1]=acc[mf][nf][2]=acc[mf][nf][3]=0.f; }

  for (int c0=0;c0<128;c0+=32){
    __syncthreads();
    for (int i=tid;i<1024;i+=256){
      int o = i>>3, c4 = (i&7)<<2;
      st_tf32_f4(&Wc[o*36 + c4], *(const float4*)&w_ff[(size_t)o*128 + c0 + c4]);
    }
    __syncthreads();
    #pragma unroll
    for (int kt=0;kt<4;kt++){
      int kk = kt*8;
      float a[2][4], b[4][2];
      #pragma unroll
      for (int mf=0;mf<2;mf++){
        int r = m0 + mf*16 + gid;
        a[mf][0] = Wc[r*36 + kk + tig];
        a[mf][1] = Wc[(r+8)*36 + kk + tig];
        a[mf][2] = Wc[r*36 + kk + 4 + tig];
        a[mf][3] = Wc[(r+8)*36 + kk + 4 + tig];
      }
      #pragma unroll
      for (int nf=0;nf<4;nf++){
        int col = n0 + nf*8 + gid;
        b[nf][0] = Xs[(c0+kk+tig)*68 + col];
        b[nf][1] = Xs[(c0+kk+4+tig)*68 + col];
      }
      #pragma unroll
      for (int mf=0;mf<2;mf++)
        #pragma unroll
        for (int nf=0;nf<4;nf++) mma8(acc[mf][nf], a[mf], b[nf]);
    }
  }
  float* zp = g_z + (size_t)npv*SLAB;
  #pragma unroll
  for (int mf=0;mf<2;mf++){
    int r = m0 + mf*16 + gid;
    float bo0 = b_ff[r], bo1 = b_ff[r+8];
    float s0a=0.f, s0b=0.f, s1a=0.f, s1b=0.f;
    #pragma unroll
    for (int nf=0;nf<4;nf++){
      int col = n0 + nf*8 + 2*tig;
      float z00 = acc[mf][nf][0]+bo0, z01 = acc[mf][nf][1]+bo0;
      float z10 = acc[mf][nf][2]+bo1, z11 = acc[mf][nf][3]+bo1;
      *(float2*)&zp[r*64 + col]     = make_float2(z00, z01);
      *(float2*)&zp[(r+8)*64 + col] = make_float2(z10, z11);
      s0a += z00+z01; s0b += z00*z00+z01*z01;
      s1a += z10+z11; s1b += z10*z10+z11*z11;
    }
    #pragma unroll
    for (int off=1; off<4; off<<=1){
      s0a += __shfl_xor_sync(0xffffffffu, s0a, off);
      s0b += __shfl_xor_sync(0xffffffffu, s0b, off);
      s1a += __shfl_xor_sync(0xffffffffu, s1a, off);
      s1b += __shfl_xor_sync(0xffffffffu, s1b, off);
    }
    if (tig==0){
      atomicAdd(&g_sum[r], s0a);   atomicAdd(&g_sq[r], s0b);
      atomicAdd(&g_sum[r+8], s1a); atomicAdd(&g_sq[r+8], s1b);
    }
  }
}

// ---------------------------------------------------------------------------
// BN apply + residual + leaky
__global__ void k_bnres(const float* __restrict__ res, const float* __restrict__ z,
                        float* __restrict__ out,
                        const float* __restrict__ gamma, const float* __restrict__ beta){
  size_t i4 = (size_t)blockIdx.x*256 + threadIdx.x;
  int c = (int)((i4 >> 4) & 127);
  float mu  = g_sum[c] * (1.0f/CNTf);
  float var = g_sq[c]  * (1.0f/CNTf) - mu*mu;
  float sc  = gamma[c] * rsqrtf(var + EPSf);
  float sh  = beta[c] - mu*sc;
  float4 zr = ((const float4*)z)[i4];
  float4 rr = ((const float4*)res)[i4];
  float4 o;
  o.x = lrelu(rr.x + zr.x*sc + sh);
  o.y = lrelu(rr.y + zr.y*sc + sh);
  o.z = lrelu(rr.z + zr.z*sc + sh);
  o.w = lrelu(rr.w + zr.w*sc + sh);
  ((float4*)out)[i4] = o;
}

__global__ void k_zero(){
  int i = threadIdx.x;
  if (i < Cd){ g_sum[i] = 0.f; g_sq[i] = 0.f; }
}

// ---------------------------------------------------------------------------
extern "C" void kernel_launch(void* const* d_in, const int* in_sizes, int n_in,
                              void* d_out, int out_size){
  const float* x     = (const float*)d_in[0];
  const float* att1  = (const float*)d_in[1];
  const float* att2  = (const float*)d_in[2];
  const float* alpt  = (const float*)d_in[3];
  const float* w_in  = (const float*)d_in[4];
  const float* b_in  = (const float*)d_in[5];
  const float* w_out = (const float*)d_in[6];
  const float* b_out = (const float*)d_in[7];
  const float* g_o   = (const float*)d_in[8];
  const float* be_o  = (const float*)d_in[9];
  const float* w_ff  = (const float*)d_in[10];
  const float* b_ff  = (const float*)d_in[11];
  const float* g_f   = (const float*)d_in[12];
  const float* be_f  = (const float*)d_in[13];

  float *px0, *px1, *py1, *pz;
  cudaGetSymbolAddress((void**)&px0, g_x0);
  cudaGetSymbolAddress((void**)&px1, g_x1);
  cudaGetSymbolAddress((void**)&py1, g_y1);
  cudaGetSymbolAddress((void**)&pz,  g_z);

  const int SM_QK = (128*68 + 192*36)*4;                     // 62464
  const int SM_AV = (128*68 + 128*68 + 64*68 + 128*36)*4;    // 105472
  const int SM_FF = (128*68 + 128*36)*4;                     // 53248
  cudaFuncSetAttribute(k_qk, cudaFuncAttributeMaxDynamicSharedMemorySize, SM_QK);
  cudaFuncSetAttribute(k_av, cudaFuncAttributeMaxDynamicSharedMemorySize, SM_AV);
  cudaFuncSetAttribute(k_ff, cudaFuncAttributeMaxDynamicSharedMemorySize, SM_FF);

  k_tin<<<dim3(256,192), dim3(32,8)>>>(x);

  auto run_block = [&](const float* attb, const float* inb, float* outb){
    k_qk <<<NPVd,256,SM_QK>>>(inb, w_in, b_in);
    k_att<<<NN*Sd*PPd,256>>>(attb, alpt);
    k_zero<<<1,128>>>();
    k_av <<<NPVd,256,SM_AV>>>(inb, w_out, b_out);
    k_bnres<<<TOTd/4/256,256>>>(inb, pz, py1, g_o, be_o);
    k_zero<<<1,128>>>();
    k_ff <<<NPVd,256,SM_FF>>>(py1, w_ff, b_ff);
    k_bnres<<<TOTd/4/256,256>>>(py1, pz, outb, g_f, be_f);
  };

  run_block(att1, px0, px1);   // block 1: x0 -> x1
  run_block(att2, px1, px0);   // block 2: x1 -> x0

  k_tout<<<dim3(256,192), dim3(32,8)>>>(px0, (float*)d_out);
}